// round 8
// baseline (speedup 1.0000x reference)
#include <cuda_runtime.h>
#include <cuda_bf16.h>
#include <math.h>

// ---------------- problem constants ----------------
#define DMODEL 1024
#define NHEAD  16
#define NKV    4
#define DK     64
#define NEXP   8
#define TOPK   2
#define RLORA  16
#define SCALE_LORA 2.0f
#define HID    4096
#define TTOK   2048
#define SEQ    1024
#define KVDIM  256
#define NSLOT  (TTOK * TOPK)

// ---------------- scratch ----------------
__device__ float d_h   [TTOK * DMODEL];
__device__ float d_WqE [DMODEL * DMODEL];
__device__ float d_WkE [DMODEL * KVDIM];
__device__ float d_WvE [DMODEL * KVDIM];
__device__ float d_gateE[DMODEL * NEXP];
__device__ float d_Q   [TTOK * DMODEL];
__device__ float d_Kb  [TTOK * KVDIM];
__device__ float d_Vb  [TTOK * KVDIM];
__device__ float d_ctx [TTOK * DMODEL];
__device__ float d_xf  [TTOK * DMODEL];
__device__ float d_h1  [NSLOT * HID];
__device__ float d_Ge  [NSLOT * DMODEL];
__device__ float d_Ve  [NSLOT * DMODEL];
__device__ int   d_top   [NSLOT];
__device__ float d_tw    [NSLOT];
__device__ int   d_pos   [NSLOT];
__device__ int   d_rowof [NSLOT];
__device__ int   d_tokrow[NSLOT];
__device__ int   d_cnt   [NEXP];
__device__ int   d_offs  [NEXP];

// ---------------- small kernels ----------------
__global__ void eff_weight_kernel(const float* __restrict__ WT,
                                  const float* __restrict__ A,
                                  const float* __restrict__ B,
                                  float* __restrict__ out, int N, int total) {
    int i = blockIdx.x * blockDim.x + threadIdx.x;
    if (i >= total) return;
    int k = i / N, n = i - k * N;
    float s = 0.f;
#pragma unroll
    for (int r = 0; r < RLORA; ++r) s += A[k * RLORA + r] * B[r * N + n];
    out[i] = WT[i] + SCALE_LORA * s;
}

__global__ void rmsnorm1_kernel(const float* __restrict__ x,
                                const float* __restrict__ w,
                                float* __restrict__ h) {
    int t = blockIdx.x;
    __shared__ float red[256];
    float ss = 0.f;
    for (int d = threadIdx.x; d < DMODEL; d += 256) {
        float v = x[(size_t)t * DMODEL + d];
        ss += v * v;
    }
    red[threadIdx.x] = ss; __syncthreads();
    for (int s = 128; s > 0; s >>= 1) {
        if (threadIdx.x < s) red[threadIdx.x] += red[threadIdx.x + s];
        __syncthreads();
    }
    float rs = rsqrtf(red[0] / (float)DMODEL + 1e-6f);
    for (int d = threadIdx.x; d < DMODEL; d += 256)
        h[(size_t)t * DMODEL + d] = x[(size_t)t * DMODEL + d] * rs * w[d];
}

__global__ void rmsnorm2_kernel(const float* __restrict__ xin,
                                const float* __restrict__ w,
                                const int* __restrict__ taskid,
                                const float* __restrict__ temb,
                                float* __restrict__ xf) {
    int t = blockIdx.x;
    __shared__ float red[256];
    float ss = 0.f;
    for (int d = threadIdx.x; d < DMODEL; d += 256) {
        float v = xin[(size_t)t * DMODEL + d];
        ss += v * v;
    }
    red[threadIdx.x] = ss; __syncthreads();
    for (int s = 128; s > 0; s >>= 1) {
        if (threadIdx.x < s) red[threadIdx.x] += red[threadIdx.x + s];
        __syncthreads();
    }
    float rs = rsqrtf(red[0] / (float)DMODEL + 1e-6f);
    int tk = taskid[t];
    for (int d = threadIdx.x; d < DMODEL; d += 256)
        xf[(size_t)t * DMODEL + d] =
            xin[(size_t)t * DMODEL + d] * rs * w[d] + temb[tk * DMODEL + d];
}

__global__ void rope_kernel(float* __restrict__ Q, float* __restrict__ K,
                            const float* __restrict__ fcos,
                            const float* __restrict__ fsin) {
    int t = blockIdx.x;
    int s = t & (SEQ - 1);
    int tid = threadIdx.x;
    int h = tid >> 5;
    int d = tid & 31;
    float c1 = fcos[s * DK + d],      s1 = fsin[s * DK + d];
    float c2 = fcos[s * DK + d + 32], s2 = fsin[s * DK + d + 32];
    {
        float* q = Q + (size_t)t * DMODEL + h * DK;
        float x1 = q[d], x2 = q[d + 32];
        q[d]      = x1 * c1 - x2 * s1;
        q[d + 32] = x2 * c2 + x1 * s2;
    }
    if (h < NKV) {
        float* k = K + (size_t)t * KVDIM + h * DK;
        float x1 = k[d], x2 = k[d + 32];
        k[d]      = x1 * c1 - x2 * s1;
        k[d + 32] = x2 * c2 + x1 * s2;
    }
}

// ---------------- fp32 tiled SGEMM: 64x64x16 (pre-routing path) -------------
#define BM 64
#define BN 64
#define BKK 16

__device__ __forceinline__ void sgemm_tile_dev(
    const float* __restrict__ A, int lda,
    const float* __restrict__ B, int ldb,
    const float* __restrict__ Cadd,
    float* __restrict__ C, int ldc,
    int M, int K, int m0, int n0)
{
    __shared__ float As[BKK][BM];
    __shared__ float Bs[BKK][BN];
    const int tid = threadIdx.x;
    const int tx = tid & 15, ty = tid >> 4;
    const int aRow = tid >> 2;
    const int aCol = (tid & 3) * 4;
    const int bRow = tid >> 4;
    const int bCol = (tid & 15) * 4;

    const float* Aptr = A + (size_t)(m0 + aRow) * lda + aCol;
    const float* Bptr = B + (size_t)bRow * ldb + n0 + bCol;

    float acc[4][4];
#pragma unroll
    for (int i = 0; i < 4; ++i)
#pragma unroll
        for (int j = 0; j < 4; ++j) acc[i][j] = 0.f;

    for (int kk = 0; kk < K; kk += BKK) {
        float4 av = *(const float4*)(Aptr + kk);
        float4 bv = *(const float4*)(Bptr + (size_t)kk * ldb);
        __syncthreads();
        As[aCol + 0][aRow] = av.x;
        As[aCol + 1][aRow] = av.y;
        As[aCol + 2][aRow] = av.z;
        As[aCol + 3][aRow] = av.w;
        *(float4*)&Bs[bRow][bCol] = bv;
        __syncthreads();
#pragma unroll
        for (int k = 0; k < BKK; ++k) {
            float4 a = *(const float4*)&As[k][ty * 4];
            float4 b = *(const float4*)&Bs[k][tx * 4];
            acc[0][0] += a.x * b.x; acc[0][1] += a.x * b.y; acc[0][2] += a.x * b.z; acc[0][3] += a.x * b.w;
            acc[1][0] += a.y * b.x; acc[1][1] += a.y * b.y; acc[1][2] += a.y * b.z; acc[1][3] += a.y * b.w;
            acc[2][0] += a.z * b.x; acc[2][1] += a.z * b.y; acc[2][2] += a.z * b.z; acc[2][3] += a.z * b.w;
            acc[3][0] += a.w * b.x; acc[3][1] += a.w * b.y; acc[3][2] += a.w * b.z; acc[3][3] += a.w * b.w;
        }
    }

#pragma unroll
    for (int i = 0; i < 4; ++i) {
        size_t crow = (size_t)(m0 + ty * 4 + i);
#pragma unroll
        for (int j = 0; j < 4; ++j) {
            int c = n0 + tx * 4 + j;
            float v = acc[i][j];
            if (Cadd) v += Cadd[crow * ldc + c];
            C[crow * ldc + c] = v;
        }
    }
}

__global__ __launch_bounds__(256) void sgemm_plain(
    const float* __restrict__ A, int lda,
    const float* __restrict__ B, int ldb,
    const float* __restrict__ Cadd,
    float* __restrict__ C, int ldc, int M, int K)
{
    sgemm_tile_dev(A, lda, B, ldb, Cadd, C, ldc, M, K,
                   blockIdx.y * BM, blockIdx.x * BN);
}

// -------- tf32 tensor-core GEMM v4: 128x64 tile, 32x32 warp tile ------------
// Lower register pressure (32-reg accumulators) -> 2 blocks/SM, so global-load
// latency of one block overlaps the other block's mma work. rna cvt on the
// smem-store side (amortized), R5 numerics.
#define TM4 128
#define TN4 64
#define TKT4 32
#define ASTR4 36    // (4*row + col) % 32 all-distinct for A frag reads
#define BSTR4 72    // (8*k + n) % 32 all-distinct for B frag reads

__device__ __forceinline__ float tf32r(float f) {
    unsigned u;
    asm("cvt.rna.tf32.f32 %0, %1;" : "=r"(u) : "f"(f));
    return __uint_as_float(u);
}

__device__ __forceinline__ void mma_tf32(float* d, const unsigned* a,
                                         const unsigned* b, const float* c) {
    asm volatile(
        "mma.sync.aligned.m16n8k8.row.col.f32.tf32.tf32.f32 "
        "{%0,%1,%2,%3}, {%4,%5,%6,%7}, {%8,%9}, {%10,%11,%12,%13};"
        : "=f"(d[0]), "=f"(d[1]), "=f"(d[2]), "=f"(d[3])
        : "r"(a[0]), "r"(a[1]), "r"(a[2]), "r"(a[3]),
          "r"(b[0]), "r"(b[1]),
          "f"(c[0]), "f"(c[1]), "f"(c[2]), "f"(c[3]));
}

__device__ __forceinline__ void mma_tile_v4(
    const float* __restrict__ A, int lda,
    const float* __restrict__ B, int ldb,
    const float* __restrict__ bias,
    float* __restrict__ C, int ldc,
    int M, int K,
    const int* __restrict__ gmap,
    int m0, int n0, int cRow0)
{
    __shared__ float Asm[TM4][ASTR4];   // 18432 B
    __shared__ float Bsm[TKT4][BSTR4];  //  9216 B  (27.6 KB total)

    const int tid  = threadIdx.x;
    const int lane = tid & 31;
    const int warp = tid >> 5;           // 0..7
    const int wm = (warp & 3) * 32;      // 4 M-positions
    const int wn = (warp >> 2) * 32;     // 2 N-positions
    const int fr = lane >> 2;
    const int fc = lane & 3;

    // A loads: 4 float4/thread; B loads: 2 float4/thread
    int aR[4], aKV[4]; bool aOK[4]; size_t aRowG[4];
#pragma unroll
    for (int i = 0; i < 4; ++i) {
        int lin = tid + i * 256;
        aR[i]  = lin >> 3;               // 0..127
        aKV[i] = (lin & 7) * 4;          // 0..28
        int gr = m0 + aR[i];
        aOK[i] = gr < M;
        aRowG[i] = aOK[i] ? (size_t)(gmap ? gmap[gr] : gr) : 0;
    }
    int bKR[2], bNV[2];
#pragma unroll
    for (int i = 0; i < 2; ++i) {
        int lin = tid + i * 256;
        bKR[i] = lin >> 4;               // 0..31
        bNV[i] = (lin & 15) * 4;         // 0..60
    }

    float acc[2][4][4];
#pragma unroll
    for (int mi = 0; mi < 2; ++mi)
#pragma unroll
        for (int ni = 0; ni < 4; ++ni)
#pragma unroll
            for (int q = 0; q < 4; ++q) acc[mi][ni][q] = 0.f;

    for (int kt = 0; kt < K; kt += TKT4) {
        float4 av[4], bv[2];
#pragma unroll
        for (int i = 0; i < 4; ++i)
            av[i] = aOK[i] ? *(const float4*)(A + aRowG[i] * lda + kt + aKV[i])
                           : make_float4(0.f, 0.f, 0.f, 0.f);
#pragma unroll
        for (int i = 0; i < 2; ++i)
            bv[i] = *(const float4*)(B + (size_t)(kt + bKR[i]) * ldb + n0 + bNV[i]);
        __syncthreads();
#pragma unroll
        for (int i = 0; i < 4; ++i) {
            float* p = &Asm[aR[i]][aKV[i]];
            p[0] = tf32r(av[i].x); p[1] = tf32r(av[i].y);
            p[2] = tf32r(av[i].z); p[3] = tf32r(av[i].w);
        }
#pragma unroll
        for (int i = 0; i < 2; ++i) {
            float* p = &Bsm[bKR[i]][bNV[i]];
            p[0] = tf32r(bv[i].x); p[1] = tf32r(bv[i].y);
            p[2] = tf32r(bv[i].z); p[3] = tf32r(bv[i].w);
        }
        __syncthreads();
#pragma unroll
        for (int k0 = 0; k0 < TKT4; k0 += 8) {
            unsigned af[2][4], bf[4][2];
#pragma unroll
            for (int mi = 0; mi < 2; ++mi) {
                int rb = wm + mi * 16;
                af[mi][0] = __float_as_uint(Asm[rb + fr][k0 + fc]);
                af[mi][1] = __float_as_uint(Asm[rb + fr + 8][k0 + fc]);
                af[mi][2] = __float_as_uint(Asm[rb + fr][k0 + fc + 4]);
                af[mi][3] = __float_as_uint(Asm[rb + fr + 8][k0 + fc + 4]);
            }
#pragma unroll
            for (int ni = 0; ni < 4; ++ni) {
                int nb = wn + ni * 8;
                bf[ni][0] = __float_as_uint(Bsm[k0 + fc][nb + fr]);
                bf[ni][1] = __float_as_uint(Bsm[k0 + fc + 4][nb + fr]);
            }
#pragma unroll
            for (int mi = 0; mi < 2; ++mi)
#pragma unroll
                for (int ni = 0; ni < 4; ++ni)
                    mma_tf32(acc[mi][ni], af[mi], bf[ni], acc[mi][ni]);
        }
        __syncthreads();
    }

    const int cc = (lane & 3) * 2;
#pragma unroll
    for (int mi = 0; mi < 2; ++mi) {
        int rloc0 = m0 + wm + mi * 16 + fr;
        int rloc1 = rloc0 + 8;
#pragma unroll
        for (int ni = 0; ni < 4; ++ni) {
            int col = n0 + wn + ni * 8 + cc;
            float b0 = bias ? bias[col] : 0.f;
            float b1 = bias ? bias[col + 1] : 0.f;
            if (rloc0 < M) {
                size_t cr = (size_t)(cRow0 + rloc0) * ldc;
                C[cr + col]     = acc[mi][ni][0] + b0;
                C[cr + col + 1] = acc[mi][ni][1] + b1;
            }
            if (rloc1 < M) {
                size_t cr = (size_t)(cRow0 + rloc1) * ldc;
                C[cr + col]     = acc[mi][ni][2] + b0;
                C[cr + col + 1] = acc[mi][ni][3] + b1;
            }
        }
    }
}

// expert GEMM dispatcher (same call shape as R5)
__global__ __launch_bounds__(256) void mma_expert(
    const float* __restrict__ A, int lda,
    const float* __restrict__ Ball, size_t bStride, int ldb,
    const float* __restrict__ biasAll, int biasStride,
    float* __restrict__ C, int ldc, int K, int useGather)
{
    int e = blockIdx.z;
    int cnt = d_cnt[e];
    int m0 = blockIdx.y * TM4;
    if (m0 >= cnt) return;
    int off = d_offs[e];
    const int* gmap = useGather ? (d_tokrow + off) : nullptr;
    const float* Aeff = useGather ? A : A + (size_t)off * lda;
    mma_tile_v4(Aeff, lda, Ball + (size_t)e * bStride, ldb,
                biasAll + (size_t)e * biasStride,
                C, ldc, cnt, K, gmap, m0, blockIdx.x * TN4, off);
}

// ---------------- flash attention (fp32, causal, GQA) ----------------
__global__ __launch_bounds__(64) void attn_kernel(
    const float* __restrict__ Q, const float* __restrict__ Kb,
    const float* __restrict__ Vb, float* __restrict__ ctx)
{
    const int qb = blockIdx.x, h = blockIdx.y, b = blockIdx.z;
    const int r = threadIdx.x;
    const int qglob = qb * 64 + r;
    const size_t t = (size_t)b * SEQ + qglob;
    const int kh = h >> 2;

    float q[DK];
    const float* qp = Q + t * DMODEL + h * DK;
#pragma unroll
    for (int d4 = 0; d4 < 16; ++d4) {
        float4 v = *(const float4*)(qp + d4 * 4);
        q[d4 * 4 + 0] = v.x; q[d4 * 4 + 1] = v.y;
        q[d4 * 4 + 2] = v.z; q[d4 * 4 + 3] = v.w;
    }
    float acc[DK];
#pragma unroll
    for (int d = 0; d < DK; ++d) acc[d] = 0.f;
    float mval = -3.4e38f, lsum = 0.f;

    __shared__ float Ksm[64][DK];
    __shared__ float Vsm[64][DK];

    for (int kt = 0; kt <= qb; ++kt) {
        __syncthreads();
        {
            size_t krow = (size_t)b * SEQ + kt * 64 + r;
            const float4* kp = (const float4*)(Kb + krow * KVDIM + kh * DK);
            const float4* vp = (const float4*)(Vb + krow * KVDIM + kh * DK);
#pragma unroll
            for (int c = 0; c < 16; ++c) {
                ((float4*)Ksm[r])[c] = kp[c];
                ((float4*)Vsm[r])[c] = vp[c];
            }
        }
        __syncthreads();
        const int kmax = (kt == qb) ? r : 63;
        for (int c0 = 0; c0 <= kmax; c0 += 16) {
            float s[16];
            float mch = -3.4e38f;
#pragma unroll
            for (int j = 0; j < 16; ++j) {
                int k = c0 + j;
                float dot = 0.f;
                const float4* kr = (const float4*)Ksm[k];
#pragma unroll
                for (int d4 = 0; d4 < 16; ++d4) {
                    float4 kv = kr[d4];
                    dot += q[d4 * 4 + 0] * kv.x + q[d4 * 4 + 1] * kv.y
                         + q[d4 * 4 + 2] * kv.z + q[d4 * 4 + 3] * kv.w;
                }
                s[j] = (k <= kmax) ? dot * 0.125f : -3.4e38f;
                mch = fmaxf(mch, s[j]);
            }
            float mnew = fmaxf(mval, mch);
            float corr = __expf(mval - mnew);
            lsum *= corr;
#pragma unroll
            for (int d = 0; d < DK; ++d) acc[d] *= corr;
#pragma unroll
            for (int j = 0; j < 16; ++j) {
                float p = __expf(s[j] - mnew);
                lsum += p;
                const float4* vr = (const float4*)Vsm[c0 + j];
#pragma unroll
                for (int d4 = 0; d4 < 16; ++d4) {
                    float4 vv = vr[d4];
                    acc[d4 * 4 + 0] += p * vv.x;
                    acc[d4 * 4 + 1] += p * vv.y;
                    acc[d4 * 4 + 2] += p * vv.z;
                    acc[d4 * 4 + 3] += p * vv.w;
                }
            }
            mval = mnew;
        }
    }
    float inv = 1.f / lsum;
    float* op = ctx + t * DMODEL + h * DK;
#pragma unroll
    for (int d = 0; d < DK; ++d) op[d] = acc[d] * inv;
}

// ---------------- gating ----------------
__global__ void gate_kernel(const float* __restrict__ xf,
                            const float* __restrict__ gateE) {
    int warp = (blockIdx.x * blockDim.x + threadIdx.x) >> 5;
    int lane = threadIdx.x & 31;
    if (warp >= TTOK) return;
    int t = warp;
    float acc[NEXP];
#pragma unroll
    for (int e = 0; e < NEXP; ++e) acc[e] = 0.f;
    for (int d = lane; d < DMODEL; d += 32) {
        float xv = xf[(size_t)t * DMODEL + d];
#pragma unroll
        for (int e = 0; e < NEXP; ++e) acc[e] += xv * gateE[d * NEXP + e];
    }
#pragma unroll
    for (int e = 0; e < NEXP; ++e)
#pragma unroll
        for (int o = 16; o > 0; o >>= 1)
            acc[e] += __shfl_xor_sync(0xffffffff, acc[e], o);
    if (lane == 0) {
        int i0 = 0; float v0 = acc[0];
#pragma unroll
        for (int e = 1; e < NEXP; ++e) if (acc[e] > v0) { v0 = acc[e]; i0 = e; }
        int i1 = -1; float v1 = -3.4e38f;
#pragma unroll
        for (int e = 0; e < NEXP; ++e)
            if (e != i0 && acc[e] > v1) { v1 = acc[e]; i1 = e; }
        if (i1 < 0) { i1 = (i0 + 1) & (NEXP - 1); v1 = v0; }
        float w0 = 1.f / (1.f + __expf(v1 - v0));
        float w1 = 1.f - w0;
        d_top[2 * t]     = i0;  d_tw[2 * t]     = w0;
        d_top[2 * t + 1] = i1;  d_tw[2 * t + 1] = w1;
    }
}

__global__ void bucket_kernel() {
    __shared__ int tops[NSLOT];
    __shared__ int cnt[NEXP];
    for (int s = threadIdx.x; s < NSLOT; s += blockDim.x) tops[s] = d_top[s];
    if (threadIdx.x < NEXP) cnt[threadIdx.x] = 0;
    __syncthreads();
    if (threadIdx.x == 0) {
        for (int s = 0; s < NSLOT; ++s) {
            int e = tops[s];
            d_pos[s] = cnt[e]++;
        }
        int o = 0;
        for (int e = 0; e < NEXP; ++e) { d_offs[e] = o; d_cnt[e] = cnt[e]; o += cnt[e]; }
    }
    __syncthreads();
    for (int s = threadIdx.x; s < NSLOT; s += blockDim.x) {
        int e = tops[s];
        int j = d_offs[e] + d_pos[s];
        d_rowof[s] = j;
        d_tokrow[j] = s >> 1;
    }
}

__global__ void combine_kernel(const float* __restrict__ Ge,
                               const float* __restrict__ Ve,
                               float* __restrict__ out) {
    int t = blockIdx.x;
    int j0 = d_rowof[2 * t],     j1 = d_rowof[2 * t + 1];
    float w0 = d_tw[2 * t],      w1 = d_tw[2 * t + 1];
    const float* g0p = Ge + (size_t)j0 * DMODEL;
    const float* v0p = Ve + (size_t)j0 * DMODEL;
    const float* g1p = Ge + (size_t)j1 * DMODEL;
    const float* v1p = Ve + (size_t)j1 * DMODEL;
    for (int d = threadIdx.x; d < DMODEL; d += blockDim.x) {
        float g0 = g0p[d], g1 = g1p[d];
        float s0 = g0 / (1.f + __expf(-g0));
        float s1 = g1 / (1.f + __expf(-g1));
        out[(size_t)t * DMODEL + d] += w0 * s0 * v0p[d] + w1 * s1 * v1p[d];
    }
}

// ---------------- launch ----------------
extern "C" void kernel_launch(void* const* d_in, const int* in_sizes, int n_in,
                              void* d_out, int out_size) {
    const float* x      = (const float*)d_in[0];
    const float* fcos   = (const float*)d_in[1];
    const float* fsin   = (const float*)d_in[2];
    const int*   taskid = (const int*)  d_in[3];
    const float* n1w    = (const float*)d_in[4];
    const float* n2w    = (const float*)d_in[5];
    const float* WqT    = (const float*)d_in[6];
    const float* WkT    = (const float*)d_in[7];
    const float* WvT    = (const float*)d_in[8];
    const float* WoT    = (const float*)d_in[9];
    const float* qA     = (const float*)d_in[10];
    const float* qB     = (const float*)d_in[11];
    const float* kA     = (const float*)d_in[12];
    const float* kB     = (const float*)d_in[13];
    const float* vA     = (const float*)d_in[14];
    const float* vB     = (const float*)d_in[15];
    const float* gateWT = (const float*)d_in[16];
    const float* gA     = (const float*)d_in[17];
    const float* gB     = (const float*)d_in[18];
    const float* temb   = (const float*)d_in[19];
    const float* eW1    = (const float*)d_in[20];
    const float* eb1    = (const float*)d_in[21];
    const float* eWg    = (const float*)d_in[22];
    const float* ebg    = (const float*)d_in[23];
    const float* eWv    = (const float*)d_in[24];
    const float* ebv    = (const float*)d_in[25];
    float* out = (float*)d_out;

    float *p_h, *p_WqE, *p_WkE, *p_WvE, *p_gateE, *p_Q, *p_Kb, *p_Vb,
          *p_ctx, *p_xf, *p_h1, *p_Ge, *p_Ve;
    cudaGetSymbolAddress((void**)&p_h,     d_h);
    cudaGetSymbolAddress((void**)&p_WqE,   d_WqE);
    cudaGetSymbolAddress((void**)&p_WkE,   d_WkE);
    cudaGetSymbolAddress((void**)&p_WvE,   d_WvE);
    cudaGetSymbolAddress((void**)&p_gateE, d_gateE);
    cudaGetSymbolAddress((void**)&p_Q,     d_Q);
    cudaGetSymbolAddress((void**)&p_Kb,    d_Kb);
    cudaGetSymbolAddress((void**)&p_Vb,    d_Vb);
    cudaGetSymbolAddress((void**)&p_ctx,   d_ctx);
    cudaGetSymbolAddress((void**)&p_xf,    d_xf);
    cudaGetSymbolAddress((void**)&p_h1,    d_h1);
    cudaGetSymbolAddress((void**)&p_Ge,    d_Ge);
    cudaGetSymbolAddress((void**)&p_Ve,    d_Ve);

    eff_weight_kernel<<<(DMODEL * DMODEL + 255) / 256, 256>>>(WqT, qA, qB, p_WqE, DMODEL, DMODEL * DMODEL);
    eff_weight_kernel<<<(DMODEL * KVDIM + 255) / 256, 256>>>(WkT, kA, kB, p_WkE, KVDIM, DMODEL * KVDIM);
    eff_weight_kernel<<<(DMODEL * KVDIM + 255) / 256, 256>>>(WvT, vA, vB, p_WvE, KVDIM, DMODEL * KVDIM);
    eff_weight_kernel<<<(DMODEL * NEXP + 255) / 256, 256>>>(gateWT, gA, gB, p_gateE, NEXP, DMODEL * NEXP);

    rmsnorm1_kernel<<<TTOK, 256>>>(x, n1w, p_h);

    // pre-routing path: exact fp32 (routing stability)
    sgemm_plain<<<dim3(DMODEL / BN, TTOK / BM), 256>>>(p_h, DMODEL, p_WqE, DMODEL, nullptr, p_Q, DMODEL, TTOK, DMODEL);
    sgemm_plain<<<dim3(KVDIM / BN, TTOK / BM), 256>>>(p_h, DMODEL, p_WkE, KVDIM, nullptr, p_Kb, KVDIM, TTOK, DMODEL);
    sgemm_plain<<<dim3(KVDIM / BN, TTOK / BM), 256>>>(p_h, DMODEL, p_WvE, KVDIM, nullptr, p_Vb, KVDIM, TTOK, DMODEL);

    rope_kernel<<<TTOK, 512>>>(p_Q, p_Kb, fcos, fsin);

    attn_kernel<<<dim3(SEQ / 64, NHEAD, 2), 64>>>(p_Q, p_Kb, p_Vb, p_ctx);

    sgemm_plain<<<dim3(DMODEL / BN, TTOK / BM), 256>>>(p_ctx, DMODEL, WoT, DMODEL, x, out, DMODEL, TTOK, DMODEL);

    rmsnorm2_kernel<<<TTOK, 256>>>(out, n2w, taskid, temb, p_xf);

    gate_kernel<<<(TTOK * 32 + 255) / 256, 256>>>(p_xf, p_gateE);
    bucket_kernel<<<1, 256>>>();

    // post-routing expert GEMMs: tf32 tensor cores, 128x64 tile (2 blocks/SM)
    mma_expert<<<dim3(HID / TN4, TTOK / TM4, NEXP), 256>>>(
        p_xf, DMODEL, eW1, (size_t)DMODEL * HID, HID, eb1, HID, p_h1, HID, DMODEL, 1);
    mma_expert<<<dim3(DMODEL / TN4, TTOK / TM4, NEXP), 256>>>(
        p_h1, HID, eWg, (size_t)HID * DMODEL, DMODEL, ebg, DMODEL, p_Ge, DMODEL, HID, 0);
    mma_expert<<<dim3(DMODEL / TN4, TTOK / TM4, NEXP), 256>>>(
        p_h1, HID, eWv, (size_t)HID * DMODEL, DMODEL, ebv, DMODEL, p_Ve, DMODEL, HID, 0);

    combine_kernel<<<TTOK, 256>>>(p_Ge, p_Ve, out);
}

// round 9
// speedup vs baseline: 1.5065x; 1.5065x over previous
#include <cuda_runtime.h>
#include <cuda_bf16.h>
#include <math.h>

// ---------------- problem constants ----------------
#define DMODEL 1024
#define NHEAD  16
#define NKV    4
#define DK     64
#define NEXP   8
#define TOPK   2
#define RLORA  16
#define SCALE_LORA 2.0f
#define HID    4096
#define TTOK   2048
#define SEQ    1024
#define KVDIM  256
#define NSLOT  (TTOK * TOPK)

// ---------------- scratch ----------------
__device__ float d_h   [TTOK * DMODEL];
__device__ float d_WqE [DMODEL * DMODEL];
__device__ float d_WkE [DMODEL * KVDIM];
__device__ float d_WvE [DMODEL * KVDIM];
__device__ float d_gateE[DMODEL * NEXP];
__device__ float d_Q   [TTOK * DMODEL];
__device__ float d_Kb  [TTOK * KVDIM];
__device__ float d_Vb  [TTOK * KVDIM];
__device__ float d_ctx [TTOK * DMODEL];
__device__ float d_xf  [TTOK * DMODEL];
__device__ float d_h1  [NSLOT * HID];
__device__ float d_Ge  [NSLOT * DMODEL];
__device__ float d_Ve  [NSLOT * DMODEL];
__device__ int   d_top   [NSLOT];
__device__ float d_tw    [NSLOT];
__device__ int   d_pos   [NSLOT];
__device__ int   d_rowof [NSLOT];
__device__ int   d_tokrow[NSLOT];
__device__ int   d_cnt   [NEXP];
__device__ int   d_offs  [NEXP];

// ---------------- small kernels ----------------
__global__ void eff_weight_kernel(const float* __restrict__ WT,
                                  const float* __restrict__ A,
                                  const float* __restrict__ B,
                                  float* __restrict__ out, int N, int total) {
    int i = blockIdx.x * blockDim.x + threadIdx.x;
    if (i >= total) return;
    int k = i / N, n = i - k * N;
    float s = 0.f;
#pragma unroll
    for (int r = 0; r < RLORA; ++r) s += A[k * RLORA + r] * B[r * N + n];
    out[i] = WT[i] + SCALE_LORA * s;
}

__global__ void rmsnorm1_kernel(const float* __restrict__ x,
                                const float* __restrict__ w,
                                float* __restrict__ h) {
    int t = blockIdx.x;
    __shared__ float red[256];
    float ss = 0.f;
    for (int d = threadIdx.x; d < DMODEL; d += 256) {
        float v = x[(size_t)t * DMODEL + d];
        ss += v * v;
    }
    red[threadIdx.x] = ss; __syncthreads();
    for (int s = 128; s > 0; s >>= 1) {
        if (threadIdx.x < s) red[threadIdx.x] += red[threadIdx.x + s];
        __syncthreads();
    }
    float rs = rsqrtf(red[0] / (float)DMODEL + 1e-6f);
    for (int d = threadIdx.x; d < DMODEL; d += 256)
        h[(size_t)t * DMODEL + d] = x[(size_t)t * DMODEL + d] * rs * w[d];
}

__global__ void rmsnorm2_kernel(const float* __restrict__ xin,
                                const float* __restrict__ w,
                                const int* __restrict__ taskid,
                                const float* __restrict__ temb,
                                float* __restrict__ xf) {
    int t = blockIdx.x;
    __shared__ float red[256];
    float ss = 0.f;
    for (int d = threadIdx.x; d < DMODEL; d += 256) {
        float v = xin[(size_t)t * DMODEL + d];
        ss += v * v;
    }
    red[threadIdx.x] = ss; __syncthreads();
    for (int s = 128; s > 0; s >>= 1) {
        if (threadIdx.x < s) red[threadIdx.x] += red[threadIdx.x + s];
        __syncthreads();
    }
    float rs = rsqrtf(red[0] / (float)DMODEL + 1e-6f);
    int tk = taskid[t];
    for (int d = threadIdx.x; d < DMODEL; d += 256)
        xf[(size_t)t * DMODEL + d] =
            xin[(size_t)t * DMODEL + d] * rs * w[d] + temb[tk * DMODEL + d];
}

__global__ void rope_kernel(float* __restrict__ Q, float* __restrict__ K,
                            const float* __restrict__ fcos,
                            const float* __restrict__ fsin) {
    int t = blockIdx.x;
    int s = t & (SEQ - 1);
    int tid = threadIdx.x;
    int h = tid >> 5;
    int d = tid & 31;
    float c1 = fcos[s * DK + d],      s1 = fsin[s * DK + d];
    float c2 = fcos[s * DK + d + 32], s2 = fsin[s * DK + d + 32];
    {
        float* q = Q + (size_t)t * DMODEL + h * DK;
        float x1 = q[d], x2 = q[d + 32];
        q[d]      = x1 * c1 - x2 * s1;
        q[d + 32] = x2 * c2 + x1 * s2;
    }
    if (h < NKV) {
        float* k = K + (size_t)t * KVDIM + h * DK;
        float x1 = k[d], x2 = k[d + 32];
        k[d]      = x1 * c1 - x2 * s1;
        k[d + 32] = x2 * c2 + x1 * s2;
    }
}

// ---------------- fp32 tiled SGEMM: 64x64x16 (pre-routing path) -------------
#define BM 64
#define BN 64
#define BKK 16

__device__ __forceinline__ void sgemm_tile_dev(
    const float* __restrict__ A, int lda,
    const float* __restrict__ B, int ldb,
    const float* __restrict__ Cadd,
    float* __restrict__ C, int ldc,
    int M, int K, int m0, int n0)
{
    __shared__ float As[BKK][BM];
    __shared__ float Bs[BKK][BN];
    const int tid = threadIdx.x;
    const int tx = tid & 15, ty = tid >> 4;
    const int aRow = tid >> 2;
    const int aCol = (tid & 3) * 4;
    const int bRow = tid >> 4;
    const int bCol = (tid & 15) * 4;

    const float* Aptr = A + (size_t)(m0 + aRow) * lda + aCol;
    const float* Bptr = B + (size_t)bRow * ldb + n0 + bCol;

    float acc[4][4];
#pragma unroll
    for (int i = 0; i < 4; ++i)
#pragma unroll
        for (int j = 0; j < 4; ++j) acc[i][j] = 0.f;

    for (int kk = 0; kk < K; kk += BKK) {
        float4 av = *(const float4*)(Aptr + kk);
        float4 bv = *(const float4*)(Bptr + (size_t)kk * ldb);
        __syncthreads();
        As[aCol + 0][aRow] = av.x;
        As[aCol + 1][aRow] = av.y;
        As[aCol + 2][aRow] = av.z;
        As[aCol + 3][aRow] = av.w;
        *(float4*)&Bs[bRow][bCol] = bv;
        __syncthreads();
#pragma unroll
        for (int k = 0; k < BKK; ++k) {
            float4 a = *(const float4*)&As[k][ty * 4];
            float4 b = *(const float4*)&Bs[k][tx * 4];
            acc[0][0] += a.x * b.x; acc[0][1] += a.x * b.y; acc[0][2] += a.x * b.z; acc[0][3] += a.x * b.w;
            acc[1][0] += a.y * b.x; acc[1][1] += a.y * b.y; acc[1][2] += a.y * b.z; acc[1][3] += a.y * b.w;
            acc[2][0] += a.z * b.x; acc[2][1] += a.z * b.y; acc[2][2] += a.z * b.z; acc[2][3] += a.z * b.w;
            acc[3][0] += a.w * b.x; acc[3][1] += a.w * b.y; acc[3][2] += a.w * b.z; acc[3][3] += a.w * b.w;
        }
    }

#pragma unroll
    for (int i = 0; i < 4; ++i) {
        size_t crow = (size_t)(m0 + ty * 4 + i);
#pragma unroll
        for (int j = 0; j < 4; ++j) {
            int c = n0 + tx * 4 + j;
            float v = acc[i][j];
            if (Cadd) v += Cadd[crow * ldc + c];
            C[crow * ldc + c] = v;
        }
    }
}

__global__ __launch_bounds__(256) void sgemm_plain(
    const float* __restrict__ A, int lda,
    const float* __restrict__ B, int ldb,
    const float* __restrict__ Cadd,
    float* __restrict__ C, int ldc, int M, int K)
{
    sgemm_tile_dev(A, lda, B, ldb, Cadd, C, ldc, M, K,
                   blockIdx.y * BM, blockIdx.x * BN);
}

// ---------------- tf32 tensor-core GEMM (R5 tile, forced 2 blocks/SM) -------
#define TM 128
#define TN 128
#define TKT 32
#define ASTR 36
#define BSTR 136

__device__ __forceinline__ float tf32r(float f) {
    unsigned u;
    asm("cvt.rna.tf32.f32 %0, %1;" : "=r"(u) : "f"(f));
    return __uint_as_float(u);
}

__device__ __forceinline__ void mma_tf32(float* d, const unsigned* a,
                                         const unsigned* b, const float* c) {
    asm volatile(
        "mma.sync.aligned.m16n8k8.row.col.f32.tf32.tf32.f32 "
        "{%0,%1,%2,%3}, {%4,%5,%6,%7}, {%8,%9}, {%10,%11,%12,%13};"
        : "=f"(d[0]), "=f"(d[1]), "=f"(d[2]), "=f"(d[3])
        : "r"(a[0]), "r"(a[1]), "r"(a[2]), "r"(a[3]),
          "r"(b[0]), "r"(b[1]),
          "f"(c[0]), "f"(c[1]), "f"(c[2]), "f"(c[3]));
}

__device__ __forceinline__ void mma_tile_dev(
    const float* __restrict__ A, int lda,
    const float* __restrict__ B, int ldb,
    const float* __restrict__ bias,
    float* __restrict__ C, int ldc,
    int M, int K,
    const int* __restrict__ gmap,
    int m0, int n0, int cRow0)
{
    __shared__ float Asm[TM][ASTR];
    __shared__ float Bsm[TKT][BSTR];
    const int tid  = threadIdx.x;
    const int lane = tid & 31;
    const int warp = tid >> 5;
    const int wm = (warp & 1) * 64;
    const int wn = (warp >> 1) * 32;
    const int fr = lane >> 2;
    const int fc = lane & 3;

    float acc[4][4][4];
#pragma unroll
    for (int mi = 0; mi < 4; ++mi)
#pragma unroll
        for (int ni = 0; ni < 4; ++ni)
#pragma unroll
            for (int q = 0; q < 4; ++q) acc[mi][ni][q] = 0.f;

    size_t arow[4]; bool avalid[4];
#pragma unroll
    for (int i = 0; i < 4; ++i) {
        int lin = tid + i * 256;
        int r = lin >> 3;
        int gr = m0 + r;
        avalid[i] = gr < M;
        arow[i] = avalid[i] ? (size_t)(gmap ? gmap[gr] : gr) : 0;
    }

    for (int kt = 0; kt < K; kt += TKT) {
        __syncthreads();
#pragma unroll
        for (int i = 0; i < 4; ++i) {
            int lin = tid + i * 256;
            int r  = lin >> 3;
            int kv = (lin & 7) * 4;
            float4 v = make_float4(0.f, 0.f, 0.f, 0.f);
            if (avalid[i]) v = *(const float4*)(A + arow[i] * lda + kt + kv);
            Asm[r][kv + 0] = tf32r(v.x);
            Asm[r][kv + 1] = tf32r(v.y);
            Asm[r][kv + 2] = tf32r(v.z);
            Asm[r][kv + 3] = tf32r(v.w);
        }
#pragma unroll
        for (int i = 0; i < 4; ++i) {
            int lin = tid + i * 256;
            int kr = lin >> 5;
            int nv = (lin & 31) * 4;
            float4 v = *(const float4*)(B + (size_t)(kt + kr) * ldb + n0 + nv);
            Bsm[kr][nv + 0] = tf32r(v.x);
            Bsm[kr][nv + 1] = tf32r(v.y);
            Bsm[kr][nv + 2] = tf32r(v.z);
            Bsm[kr][nv + 3] = tf32r(v.w);
        }
        __syncthreads();
#pragma unroll
        for (int k0 = 0; k0 < TKT; k0 += 8) {
            unsigned af[4][4], bf[4][2];
#pragma unroll
            for (int mi = 0; mi < 4; ++mi) {
                int rb = wm + mi * 16;
                af[mi][0] = __float_as_uint(Asm[rb + fr][k0 + fc]);
                af[mi][1] = __float_as_uint(Asm[rb + fr + 8][k0 + fc]);
                af[mi][2] = __float_as_uint(Asm[rb + fr][k0 + fc + 4]);
                af[mi][3] = __float_as_uint(Asm[rb + fr + 8][k0 + fc + 4]);
            }
#pragma unroll
            for (int ni = 0; ni < 4; ++ni) {
                int nb = wn + ni * 8;
                bf[ni][0] = __float_as_uint(Bsm[k0 + fc][nb + fr]);
                bf[ni][1] = __float_as_uint(Bsm[k0 + fc + 4][nb + fr]);
            }
#pragma unroll
            for (int mi = 0; mi < 4; ++mi)
#pragma unroll
                for (int ni = 0; ni < 4; ++ni)
                    mma_tf32(acc[mi][ni], af[mi], bf[ni], acc[mi][ni]);
        }
    }

    const int cc = (lane & 3) * 2;
#pragma unroll
    for (int mi = 0; mi < 4; ++mi) {
        int rloc0 = m0 + wm + mi * 16 + fr;
        int rloc1 = rloc0 + 8;
#pragma unroll
        for (int ni = 0; ni < 4; ++ni) {
            int col = n0 + wn + ni * 8 + cc;
            float b0 = bias ? bias[col] : 0.f;
            float b1 = bias ? bias[col + 1] : 0.f;
            if (rloc0 < M) {
                size_t cr = (size_t)(cRow0 + rloc0) * ldc;
                C[cr + col]     = acc[mi][ni][0] + b0;
                C[cr + col + 1] = acc[mi][ni][1] + b1;
            }
            if (rloc1 < M) {
                size_t cr = (size_t)(cRow0 + rloc1) * ldc;
                C[cr + col]     = acc[mi][ni][2] + b0;
                C[cr + col + 1] = acc[mi][ni][3] + b1;
            }
        }
    }
}

// forced 2 blocks/SM: caps registers at 128 so two CTAs overlap load/compute
__global__ __launch_bounds__(256, 2) void mma_expert(
    const float* __restrict__ A, int lda,
    const float* __restrict__ Ball, size_t bStride, int ldb,
    const float* __restrict__ biasAll, int biasStride,
    float* __restrict__ C, int ldc, int K, int useGather)
{
    int e = blockIdx.z;
    int cnt = d_cnt[e];
    int m0 = blockIdx.y * TM;
    if (m0 >= cnt) return;
    int off = d_offs[e];
    const int* gmap = useGather ? (d_tokrow + off) : nullptr;
    const float* Aeff = useGather ? A : A + (size_t)off * lda;
    mma_tile_dev(Aeff, lda, Ball + (size_t)e * bStride, ldb,
                 biasAll + (size_t)e * biasStride,
                 C, ldc, cnt, K, gmap, m0, blockIdx.x * TN, off);
}

// ---------------- flash attention (fp32, causal, GQA) ----------------
__global__ __launch_bounds__(64) void attn_kernel(
    const float* __restrict__ Q, const float* __restrict__ Kb,
    const float* __restrict__ Vb, float* __restrict__ ctx)
{
    const int qb = blockIdx.x, h = blockIdx.y, b = blockIdx.z;
    const int r = threadIdx.x;
    const int qglob = qb * 64 + r;
    const size_t t = (size_t)b * SEQ + qglob;
    const int kh = h >> 2;

    float q[DK];
    const float* qp = Q + t * DMODEL + h * DK;
#pragma unroll
    for (int d4 = 0; d4 < 16; ++d4) {
        float4 v = *(const float4*)(qp + d4 * 4);
        q[d4 * 4 + 0] = v.x; q[d4 * 4 + 1] = v.y;
        q[d4 * 4 + 2] = v.z; q[d4 * 4 + 3] = v.w;
    }
    float acc[DK];
#pragma unroll
    for (int d = 0; d < DK; ++d) acc[d] = 0.f;
    float mval = -3.4e38f, lsum = 0.f;

    __shared__ float Ksm[64][DK];
    __shared__ float Vsm[64][DK];

    for (int kt = 0; kt <= qb; ++kt) {
        __syncthreads();
        {
            size_t krow = (size_t)b * SEQ + kt * 64 + r;
            const float4* kp = (const float4*)(Kb + krow * KVDIM + kh * DK);
            const float4* vp = (const float4*)(Vb + krow * KVDIM + kh * DK);
#pragma unroll
            for (int c = 0; c < 16; ++c) {
                ((float4*)Ksm[r])[c] = kp[c];
                ((float4*)Vsm[r])[c] = vp[c];
            }
        }
        __syncthreads();
        const int kmax = (kt == qb) ? r : 63;
        for (int c0 = 0; c0 <= kmax; c0 += 16) {
            float s[16];
            float mch = -3.4e38f;
#pragma unroll
            for (int j = 0; j < 16; ++j) {
                int k = c0 + j;
                float dot = 0.f;
                const float4* kr = (const float4*)Ksm[k];
#pragma unroll
                for (int d4 = 0; d4 < 16; ++d4) {
                    float4 kv = kr[d4];
                    dot += q[d4 * 4 + 0] * kv.x + q[d4 * 4 + 1] * kv.y
                         + q[d4 * 4 + 2] * kv.z + q[d4 * 4 + 3] * kv.w;
                }
                s[j] = (k <= kmax) ? dot * 0.125f : -3.4e38f;
                mch = fmaxf(mch, s[j]);
            }
            float mnew = fmaxf(mval, mch);
            float corr = __expf(mval - mnew);
            lsum *= corr;
#pragma unroll
            for (int d = 0; d < DK; ++d) acc[d] *= corr;
#pragma unroll
            for (int j = 0; j < 16; ++j) {
                float p = __expf(s[j] - mnew);
                lsum += p;
                const float4* vr = (const float4*)Vsm[c0 + j];
#pragma unroll
                for (int d4 = 0; d4 < 16; ++d4) {
                    float4 vv = vr[d4];
                    acc[d4 * 4 + 0] += p * vv.x;
                    acc[d4 * 4 + 1] += p * vv.y;
                    acc[d4 * 4 + 2] += p * vv.z;
                    acc[d4 * 4 + 3] += p * vv.w;
                }
            }
            mval = mnew;
        }
    }
    float inv = 1.f / lsum;
    float* op = ctx + t * DMODEL + h * DK;
#pragma unroll
    for (int d = 0; d < DK; ++d) op[d] = acc[d] * inv;
}

// ---------------- gating ----------------
__global__ void gate_kernel(const float* __restrict__ xf,
                            const float* __restrict__ gateE) {
    int warp = (blockIdx.x * blockDim.x + threadIdx.x) >> 5;
    int lane = threadIdx.x & 31;
    if (warp >= TTOK) return;
    int t = warp;
    float acc[NEXP];
#pragma unroll
    for (int e = 0; e < NEXP; ++e) acc[e] = 0.f;
    for (int d = lane; d < DMODEL; d += 32) {
        float xv = xf[(size_t)t * DMODEL + d];
#pragma unroll
        for (int e = 0; e < NEXP; ++e) acc[e] += xv * gateE[d * NEXP + e];
    }
#pragma unroll
    for (int e = 0; e < NEXP; ++e)
#pragma unroll
        for (int o = 16; o > 0; o >>= 1)
            acc[e] += __shfl_xor_sync(0xffffffff, acc[e], o);
    if (lane == 0) {
        int i0 = 0; float v0 = acc[0];
#pragma unroll
        for (int e = 1; e < NEXP; ++e) if (acc[e] > v0) { v0 = acc[e]; i0 = e; }
        int i1 = -1; float v1 = -3.4e38f;
#pragma unroll
        for (int e = 0; e < NEXP; ++e)
            if (e != i0 && acc[e] > v1) { v1 = acc[e]; i1 = e; }
        if (i1 < 0) { i1 = (i0 + 1) & (NEXP - 1); v1 = v0; }
        float w0 = 1.f / (1.f + __expf(v1 - v0));
        float w1 = 1.f - w0;
        d_top[2 * t]     = i0;  d_tw[2 * t]     = w0;
        d_top[2 * t + 1] = i1;  d_tw[2 * t + 1] = w1;
    }
}

__global__ void bucket_kernel() {
    __shared__ int tops[NSLOT];
    __shared__ int cnt[NEXP];
    for (int s = threadIdx.x; s < NSLOT; s += blockDim.x) tops[s] = d_top[s];
    if (threadIdx.x < NEXP) cnt[threadIdx.x] = 0;
    __syncthreads();
    if (threadIdx.x == 0) {
        for (int s = 0; s < NSLOT; ++s) {
            int e = tops[s];
            d_pos[s] = cnt[e]++;
        }
        int o = 0;
        for (int e = 0; e < NEXP; ++e) { d_offs[e] = o; d_cnt[e] = cnt[e]; o += cnt[e]; }
    }
    __syncthreads();
    for (int s = threadIdx.x; s < NSLOT; s += blockDim.x) {
        int e = tops[s];
        int j = d_offs[e] + d_pos[s];
        d_rowof[s] = j;
        d_tokrow[j] = s >> 1;
    }
}

// out[t] += sum_k w_k * silu(Ge[j_k]) * Ve[j_k]   (float4 vectorized)
__global__ void combine_kernel(const float* __restrict__ Ge,
                               const float* __restrict__ Ve,
                               float* __restrict__ out) {
    int t = blockIdx.x;
    int j0 = d_rowof[2 * t],     j1 = d_rowof[2 * t + 1];
    float w0 = d_tw[2 * t],      w1 = d_tw[2 * t + 1];
    const float4* g0p = (const float4*)(Ge + (size_t)j0 * DMODEL);
    const float4* v0p = (const float4*)(Ve + (size_t)j0 * DMODEL);
    const float4* g1p = (const float4*)(Ge + (size_t)j1 * DMODEL);
    const float4* v1p = (const float4*)(Ve + (size_t)j1 * DMODEL);
    float4* op = (float4*)(out + (size_t)t * DMODEL);
    for (int d = threadIdx.x; d < DMODEL / 4; d += blockDim.x) {
        float4 g0 = g0p[d], g1 = g1p[d], v0 = v0p[d], v1 = v1p[d], o = op[d];
        o.x += w0 * (g0.x / (1.f + __expf(-g0.x))) * v0.x + w1 * (g1.x / (1.f + __expf(-g1.x))) * v1.x;
        o.y += w0 * (g0.y / (1.f + __expf(-g0.y))) * v0.y + w1 * (g1.y / (1.f + __expf(-g1.y))) * v1.y;
        o.z += w0 * (g0.z / (1.f + __expf(-g0.z))) * v0.z + w1 * (g1.z / (1.f + __expf(-g1.z))) * v1.z;
        o.w += w0 * (g0.w / (1.f + __expf(-g0.w))) * v0.w + w1 * (g1.w / (1.f + __expf(-g1.w))) * v1.w;
        op[d] = o;
    }
}

// ---------------- launch ----------------
extern "C" void kernel_launch(void* const* d_in, const int* in_sizes, int n_in,
                              void* d_out, int out_size) {
    const float* x      = (const float*)d_in[0];
    const float* fcos   = (const float*)d_in[1];
    const float* fsin   = (const float*)d_in[2];
    const int*   taskid = (const int*)  d_in[3];
    const float* n1w    = (const float*)d_in[4];
    const float* n2w    = (const float*)d_in[5];
    const float* WqT    = (const float*)d_in[6];
    const float* WkT    = (const float*)d_in[7];
    const float* WvT    = (const float*)d_in[8];
    const float* WoT    = (const float*)d_in[9];
    const float* qA     = (const float*)d_in[10];
    const float* qB     = (const float*)d_in[11];
    const float* kA     = (const float*)d_in[12];
    const float* kB     = (const float*)d_in[13];
    const float* vA     = (const float*)d_in[14];
    const float* vB     = (const float*)d_in[15];
    const float* gateWT = (const float*)d_in[16];
    const float* gA     = (const float*)d_in[17];
    const float* gB     = (const float*)d_in[18];
    const float* temb   = (const float*)d_in[19];
    const float* eW1    = (const float*)d_in[20];
    const float* eb1    = (const float*)d_in[21];
    const float* eWg    = (const float*)d_in[22];
    const float* ebg    = (const float*)d_in[23];
    const float* eWv    = (const float*)d_in[24];
    const float* ebv    = (const float*)d_in[25];
    float* out = (float*)d_out;

    float *p_h, *p_WqE, *p_WkE, *p_WvE, *p_gateE, *p_Q, *p_Kb, *p_Vb,
          *p_ctx, *p_xf, *p_h1, *p_Ge, *p_Ve;
    cudaGetSymbolAddress((void**)&p_h,     d_h);
    cudaGetSymbolAddress((void**)&p_WqE,   d_WqE);
    cudaGetSymbolAddress((void**)&p_WkE,   d_WkE);
    cudaGetSymbolAddress((void**)&p_WvE,   d_WvE);
    cudaGetSymbolAddress((void**)&p_gateE, d_gateE);
    cudaGetSymbolAddress((void**)&p_Q,     d_Q);
    cudaGetSymbolAddress((void**)&p_Kb,    d_Kb);
    cudaGetSymbolAddress((void**)&p_Vb,    d_Vb);
    cudaGetSymbolAddress((void**)&p_ctx,   d_ctx);
    cudaGetSymbolAddress((void**)&p_xf,    d_xf);
    cudaGetSymbolAddress((void**)&p_h1,    d_h1);
    cudaGetSymbolAddress((void**)&p_Ge,    d_Ge);
    cudaGetSymbolAddress((void**)&p_Ve,    d_Ve);

    eff_weight_kernel<<<(DMODEL * DMODEL + 255) / 256, 256>>>(WqT, qA, qB, p_WqE, DMODEL, DMODEL * DMODEL);
    eff_weight_kernel<<<(DMODEL * KVDIM + 255) / 256, 256>>>(WkT, kA, kB, p_WkE, KVDIM, DMODEL * KVDIM);
    eff_weight_kernel<<<(DMODEL * KVDIM + 255) / 256, 256>>>(WvT, vA, vB, p_WvE, KVDIM, DMODEL * KVDIM);
    eff_weight_kernel<<<(DMODEL * NEXP + 255) / 256, 256>>>(gateWT, gA, gB, p_gateE, NEXP, DMODEL * NEXP);

    rmsnorm1_kernel<<<TTOK, 256>>>(x, n1w, p_h);

    // pre-routing path: exact fp32 (routing stability)
    sgemm_plain<<<dim3(DMODEL / BN, TTOK / BM), 256>>>(p_h, DMODEL, p_WqE, DMODEL, nullptr, p_Q, DMODEL, TTOK, DMODEL);
    sgemm_plain<<<dim3(KVDIM / BN, TTOK / BM), 256>>>(p_h, DMODEL, p_WkE, KVDIM, nullptr, p_Kb, KVDIM, TTOK, DMODEL);
    sgemm_plain<<<dim3(KVDIM / BN, TTOK / BM), 256>>>(p_h, DMODEL, p_WvE, KVDIM, nullptr, p_Vb, KVDIM, TTOK, DMODEL);

    rope_kernel<<<TTOK, 512>>>(p_Q, p_Kb, fcos, fsin);

    attn_kernel<<<dim3(SEQ / 64, NHEAD, 2), 64>>>(p_Q, p_Kb, p_Vb, p_ctx);

    sgemm_plain<<<dim3(DMODEL / BN, TTOK / BM), 256>>>(p_ctx, DMODEL, WoT, DMODEL, x, out, DMODEL, TTOK, DMODEL);

    rmsnorm2_kernel<<<TTOK, 256>>>(out, n2w, taskid, temb, p_xf);

    gate_kernel<<<(TTOK * 32 + 255) / 256, 256>>>(p_xf, p_gateE);
    bucket_kernel<<<1, 256>>>();

    // post-routing expert GEMMs: R5 tile, forced 2 blocks/SM
    mma_expert<<<dim3(HID / TN, TTOK / TM, NEXP), 256>>>(
        p_xf, DMODEL, eW1, (size_t)DMODEL * HID, HID, eb1, HID, p_h1, HID, DMODEL, 1);
    mma_expert<<<dim3(DMODEL / TN, TTOK / TM, NEXP), 256>>>(
        p_h1, HID, eWg, (size_t)HID * DMODEL, DMODEL, ebg, DMODEL, p_Ge, DMODEL, HID, 0);
    mma_expert<<<dim3(DMODEL / TN, TTOK / TM, NEXP), 256>>>(
        p_h1, HID, eWv, (size_t)HID * DMODEL, DMODEL, ebv, DMODEL, p_Ve, DMODEL, HID, 0);

    combine_kernel<<<TTOK, 256>>>(p_Ge, p_Ve, out);
}